// round 15
// baseline (speedup 1.0000x reference)
#include <cuda_runtime.h>
#include <cuda_fp16.h>
#include <cstdint>

#define BB 8
#define TT 4096
#define DD 512
#define HH 64

// device-global scratch (allocation-free)
__device__ __half g_qh[BB * TT * HH];            // [b*T + t][h] (pre-scaled by scale*log2e)
__device__ __half g_kh[BB * TT * HH];            // [b*T + t][h]
__device__ __half g_vt[BB * HH * TT];            // [b][h][t]  (V transposed)
__device__ __half g_w3h[DD * 192];               // fp16 W interleaved [k][m*64+n]
#define NCHUNK 144                               // key-chunks per batch
__device__ __half g_po[BB * NCHUNK * 128 * 64];  // partial O (unnormalized, fp16)
__device__ float  g_pl[BB * NCHUNK * 128];       // partial l
__device__ int    g_cnt[BB * 32];                // per-(b,g) completion counters

__device__ __forceinline__ uint32_t smem_to_u32(const void* p) {
    uint32_t a;
    asm("{ .reg .u64 t; cvta.to.shared.u64 t, %1; cvt.u32.u64 %0, t; }" : "=r"(a) : "l"(p));
    return a;
}
#define CP_ASYNC16(dst, src) \
    asm volatile("cp.async.cg.shared.global [%0], [%1], 16;" :: "r"(dst), "l"(src))
#define CP_COMMIT() asm volatile("cp.async.commit_group;")
#define CP_WAIT0()  asm volatile("cp.async.wait_group 0;" ::: "memory")

#define MMA_F16(d, a, b0, b1) \
    asm volatile("mma.sync.aligned.m16n8k16.row.col.f32.f16.f16.f32 " \
        "{%0,%1,%2,%3}, {%4,%5,%6,%7}, {%8,%9}, {%0,%1,%2,%3};" \
        : "+f"((d)[0]), "+f"((d)[1]), "+f"((d)[2]), "+f"((d)[3]) \
        : "r"((a)[0]), "r"((a)[1]), "r"((a)[2]), "r"((a)[3]), "r"(b0), "r"(b1))

// scale * log2(e), folded into Wq
#define SCL2E 0.06376259339187951f

// ---------------------------------------------------------------------------
// W pre-conversion: fp32 -> fp16, interleaved [k][m*64+n]; Wq scaled by SCL2E
// ---------------------------------------------------------------------------
__global__ __launch_bounds__(256) void conv_w(
    const float* __restrict__ Wq, const float* __restrict__ Wk, const float* __restrict__ Wv)
{
    int gid = blockIdx.x * 256 + threadIdx.x;      // 12288 threads, 8 halves each
    int col = (gid * 8) % 192;
    int k   = (gid * 8) / 192;
    int m   = col / 64;
    int n   = col % 64;
    const float* W = (m == 0) ? Wq : ((m == 1) ? Wk : Wv);
    const float sc = (m == 0) ? SCL2E : 1.0f;
    float4 a = *(const float4*)&W[(size_t)k * HH + n];
    float4 b = *(const float4*)&W[(size_t)k * HH + n + 4];
    __half2 h0 = __floats2half2_rn(a.x * sc, a.y * sc);
    __half2 h1 = __floats2half2_rn(a.z * sc, a.w * sc);
    __half2 h2 = __floats2half2_rn(b.x * sc, b.y * sc);
    __half2 h3 = __floats2half2_rn(b.z * sc, b.w * sc);
    uint4 o;
    o.x = *(uint32_t*)&h0; o.y = *(uint32_t*)&h1;
    o.z = *(uint32_t*)&h2; o.w = *(uint32_t*)&h3;
    *(uint4*)&g_w3h[(size_t)k * 192 + col] = o;
}

// ---------------------------------------------------------------------------
// Kernel 1: QKV projection. 64-row CTA tiles, fp32 X loaded direct via LDG
// register prefetch (cvt->STS), W fp16 cp.async double-buffered.
// ---------------------------------------------------------------------------
#define XP 72    // X tile pitch (halves)
#define WP 200   // W tile pitch (halves)
#define VP 72    // V staging pitch (halves)
#define PX0 0
#define PX1 9216
#define PW0 18432
#define PW1 44032
#define PROJ_SMEM 69632

__device__ __forceinline__ void w_cp(uint32_t smb, int kc, int buf, int tid)
{
    const __half* wsrc = g_w3h + (size_t)(kc * 64) * 192;
    const uint32_t wb = smb + (buf ? PW1 : PW0);
    #pragma unroll
    for (int it = 0; it < 6; ++it) {
        int idx = tid + it * 256;                  // 0..1535
        int r = idx / 24, c = idx % 24;
        CP_ASYNC16(wb + (uint32_t)(r * (WP * 2) + c * 16), wsrc + (size_t)r * 192 + c * 8);
    }
}

__global__ __launch_bounds__(256, 2) void proj_mma(const float* __restrict__ x)
{
    extern __shared__ __align__(16) char psm[];
    const uint32_t smb = smem_to_u32(psm);
    __half* Vst = (__half*)psm;                    // reuses X buffers after mainloop

    const int tid  = threadIdx.x;
    const int warp = tid >> 5;
    const int lane = tid & 31;
    const int wm   = warp >> 2;                    // 0..1 (32 rows each)
    const int wn   = warp & 3;                     // 0..3 (48 cols each)
    const int row0 = blockIdx.x * 64;

    float acc[2][6][4];
    #pragma unroll
    for (int mt = 0; mt < 2; ++mt)
        #pragma unroll
        for (int nt = 0; nt < 6; ++nt)
            acc[mt][nt][0] = acc[mt][nt][1] = acc[mt][nt][2] = acc[mt][nt][3] = 0.f;

    float4 xr[4];
    #pragma unroll
    for (int it = 0; it < 4; ++it) {
        int idx = tid + it * 256;
        int r = idx >> 4, c4 = (idx & 15) * 4;
        xr[it] = *(const float4*)&x[(size_t)(row0 + r) * DD + 0 * 64 + c4];
    }
    {
        __half* Xb = (__half*)(psm + PX0);
        #pragma unroll
        for (int it = 0; it < 4; ++it) {
            int idx = tid + it * 256;
            int r = idx >> 4, c4 = (idx & 15) * 4;
            __half2 h0 = __floats2half2_rn(xr[it].x, xr[it].y);
            __half2 h1 = __floats2half2_rn(xr[it].z, xr[it].w);
            uint2 pk; pk.x = *(uint32_t*)&h0; pk.y = *(uint32_t*)&h1;
            *(uint2*)&Xb[r * XP + c4] = pk;
        }
    }
    w_cp(smb, 0, 0, tid);
    CP_COMMIT();
    #pragma unroll
    for (int it = 0; it < 4; ++it) {
        int idx = tid + it * 256;
        int r = idx >> 4, c4 = (idx & 15) * 4;
        xr[it] = *(const float4*)&x[(size_t)(row0 + r) * DD + 1 * 64 + c4];
    }
    CP_WAIT0();
    __syncthreads();

    for (int kc = 0; kc < 8; ++kc) {
        if (kc < 7) { w_cp(smb, kc + 1, (kc + 1) & 1, tid); CP_COMMIT(); }

        const uint32_t xb = smb + ((kc & 1) ? PX1 : PX0);
        const uint32_t wb = smb + ((kc & 1) ? PW1 : PW0);

        #pragma unroll
        for (int ks = 0; ks < 4; ++ks) {
            uint32_t a[2][4];
            #pragma unroll
            for (int mt = 0; mt < 2; ++mt) {
                int row = wm * 32 + mt * 16 + (lane & 7) + ((lane >> 3) & 1) * 8;
                int col = ks * 16 + ((lane >> 4) << 3);
                uint32_t ad = xb + (uint32_t)(row * XP + col) * 2;
                asm volatile("ldmatrix.sync.aligned.m8n8.x4.shared.b16 {%0,%1,%2,%3}, [%4];"
                    : "=r"(a[mt][0]), "=r"(a[mt][1]), "=r"(a[mt][2]), "=r"(a[mt][3])
                    : "r"(ad));
            }
            #pragma unroll
            for (int nt = 0; nt < 6; ++nt) {
                uint32_t b0, b1;
                uint32_t ad = wb +
                    (uint32_t)((ks * 16 + (lane & 15)) * WP + wn * 48 + nt * 8) * 2;
                asm volatile("ldmatrix.sync.aligned.m8n8.x2.trans.shared.b16 {%0,%1}, [%2];"
                    : "=r"(b0), "=r"(b1) : "r"(ad));
                #pragma unroll
                for (int mt = 0; mt < 2; ++mt)
                    MMA_F16(acc[mt][nt], a[mt], b0, b1);
            }
        }

        if (kc < 7) {
            __half* Xb = (__half*)(psm + (((kc + 1) & 1) ? PX1 : PX0));
            #pragma unroll
            for (int it = 0; it < 4; ++it) {
                int idx = tid + it * 256;
                int r = idx >> 4, c4 = (idx & 15) * 4;
                __half2 h0 = __floats2half2_rn(xr[it].x, xr[it].y);
                __half2 h1 = __floats2half2_rn(xr[it].z, xr[it].w);
                uint2 pk; pk.x = *(uint32_t*)&h0; pk.y = *(uint32_t*)&h1;
                *(uint2*)&Xb[r * XP + c4] = pk;
            }
            if (kc < 6) {
                #pragma unroll
                for (int it = 0; it < 4; ++it) {
                    int idx = tid + it * 256;
                    int r = idx >> 4, c4 = (idx & 15) * 4;
                    xr[it] = *(const float4*)&x[(size_t)(row0 + r) * DD + (kc + 2) * 64 + c4];
                }
            }
            CP_WAIT0();
        }
        __syncthreads();
    }

    // ---- store Q/K direct; stage V for transposed coalesced write ----
    const int rA = lane >> 2;
    const int cA = (lane & 3) * 2;
    #pragma unroll
    for (int mt = 0; mt < 2; ++mt) {
        #pragma unroll
        for (int nt = 0; nt < 6; ++nt) {
            const int n0 = wn * 48 + nt * 8 + cA;
            const int r  = wm * 32 + mt * 16 + rA;
            if (n0 < 128) {
                __half* dst = (n0 < 64) ? g_qh : g_kh;
                const int nn = n0 & 63;
                *(__half2*)&dst[(size_t)(row0 + r) * HH + nn] =
                    __floats2half2_rn(acc[mt][nt][0], acc[mt][nt][1]);
                *(__half2*)&dst[(size_t)(row0 + r + 8) * HH + nn] =
                    __floats2half2_rn(acc[mt][nt][2], acc[mt][nt][3]);
            } else {
                const int h = n0 - 128;
                Vst[h * VP + r]           = __float2half(acc[mt][nt][0]);
                Vst[(h + 1) * VP + r]     = __float2half(acc[mt][nt][1]);
                Vst[h * VP + r + 8]       = __float2half(acc[mt][nt][2]);
                Vst[(h + 1) * VP + r + 8] = __float2half(acc[mt][nt][3]);
            }
        }
    }
    __syncthreads();

    const int b  = row0 >> 12;
    const int t0 = row0 & (TT - 1);
    #pragma unroll
    for (int it = 0; it < 2; ++it) {
        int idx = tid + it * 256;                  // 0..511
        int h = idx >> 3, tc = (idx & 7) * 8;
        uint4 v = *(uint4*)&Vst[h * VP + tc];
        *(uint4*)&g_vt[((size_t)b * HH + h) * TT + t0 + tc] = v;
    }
}

// ---------------------------------------------------------------------------
// Kernel 2: split-K flash chunks (8 warps, 16 q-rows per warp) with FUSED
// reduction: nc==1 groups write out directly; nc>1 groups use a per-(b,g)
// atomic counter and the last-finishing CTA reduces + normalizes.
// ---------------------------------------------------------------------------
#define PITCH 72
#define QOFF  0
#define KOFF0 18432
#define KOFF1 27648
#define VOFF0 36864
#define VOFF1 46080
#define FLASH_SMEM 55296

__device__ __forceinline__ void kv_cp(uint32_t smb, const __half* kg, const __half* vtg,
                                      int j0, int buf, int tid)
{
    const uint32_t kb = smb + (buf ? KOFF1 : KOFF0);
    const uint32_t vb = smb + (buf ? VOFF1 : VOFF0);
    #pragma unroll
    for (int it = 0; it < 2; ++it) {
        int idx = tid + it * 256;
        int r = idx >> 3, c = idx & 7;
        CP_ASYNC16(kb + (uint32_t)(r * (PITCH * 2) + c * 16),
                   kg + (size_t)(j0 + r) * HH + c * 8);
        CP_ASYNC16(vb + (uint32_t)(r * (PITCH * 2) + c * 16),
                   vtg + (size_t)r * TT + j0 + c * 8);
    }
}

__global__ __launch_bounds__(256, 2) void flash_chunk(float* __restrict__ out)
{
    extern __shared__ __align__(16) char sm[];
    const uint32_t smb = smem_to_u32(sm);

    const int tid  = threadIdx.x;
    const int warp = tid >> 5;
    const int lane = tid & 31;
    const int b    = blockIdx.y;

    // decode work item -> (g, c)
    int g = 0, cch = 0;
    {
        int it = blockIdx.x, off = 0;
        #pragma unroll 1
        for (int gg = 0; gg < 32; ++gg) {
            int cg = (2 * gg + 9) >> 3;
            if (it < off + cg) { g = gg; cch = it - off; break; }
            off += cg;
        }
    }
    const int qi0 = g * 128;
    const int t0  = cch * 8;
    const int t1  = min(t0 + 8, 2 * g + 2);
    const int nc  = (2 * g + 9) >> 3;

    const __half* qg  = g_qh + ((size_t)b * TT + qi0) * HH;
    const __half* kg  = g_kh + (size_t)b * TT * HH;
    const __half* vtg = g_vt + (size_t)b * HH * TT;

    // prologue: Q + first K/V tile
    #pragma unroll
    for (int it = 0; it < 4; ++it) {
        int idx = tid + it * 256;
        int r = idx >> 3, c = idx & 7;
        CP_ASYNC16(smb + QOFF + (uint32_t)(r * (PITCH * 2) + c * 16),
                   qg + (size_t)r * HH + c * 8);
    }
    kv_cp(smb, kg, vtg, t0 * 64, t0 & 1, tid);
    CP_COMMIT();
    CP_WAIT0();
    __syncthreads();

    // Q A-fragments
    const int mrow = warp * 16;
    uint32_t aq[4][4];
    {
        int row = mrow + (lane & 7) + ((lane >> 3) & 1) * 8;
        int col = ((lane >> 4) << 3);
        #pragma unroll
        for (int ks = 0; ks < 4; ++ks) {
            uint32_t ad = smb + QOFF + (uint32_t)(row * PITCH + ks * 16 + col) * 2;
            asm volatile("ldmatrix.sync.aligned.m8n8.x4.shared.b16 {%0,%1,%2,%3}, [%4];"
                : "=r"(aq[ks][0]), "=r"(aq[ks][1]), "=r"(aq[ks][2]), "=r"(aq[ks][3])
                : "r"(ad));
        }
    }

    const int lr0 = mrow + (lane >> 2);           // local rows
    const int lr1 = lr0 + 8;
    const int r0g = qi0 + lr0;                    // global rows (for mask)
    const int r1g = r0g + 8;
    const int cql = (lane & 3) * 2;

    float o[8][4];
    #pragma unroll
    for (int n = 0; n < 8; ++n)
        #pragma unroll
        for (int i = 0; i < 4; ++i) o[n][i] = 0.f;
    float lacc[4] = {0.f, 0.f, 0.f, 0.f};         // l via P x ones MMA
    const uint32_t ONE2 = 0x3C003C00u;            // half2(1.0, 1.0)

    const int b4r = ((lane >> 4) << 3) + (lane & 7);
    const int b4c = ((lane >> 3) & 1) * 8;

    for (int t = t0; t < t1; ++t) {
        if (t + 1 < t1) { kv_cp(smb, kg, vtg, (t + 1) * 64, (t + 1) & 1, tid); CP_COMMIT(); }

        const uint32_t kbase = smb + ((t & 1) ? KOFF1 : KOFF0);
        const uint32_t vbase = smb + ((t & 1) ? VOFF1 : VOFF0);
        const int j0 = t * 64;

        // ---- S = Q K^T (x4 B loads: 2 j-tiles per ldmatrix) ----
        float s[8][4];
        #pragma unroll
        for (int n = 0; n < 8; n += 2) {
            s[n][0] = s[n][1] = s[n][2] = s[n][3] = 0.f;
            s[n+1][0] = s[n+1][1] = s[n+1][2] = s[n+1][3] = 0.f;
            #pragma unroll
            for (int ks = 0; ks < 4; ++ks) {
                uint32_t b0, b1, b2, b3;
                uint32_t ad = kbase + (uint32_t)((n * 8 + b4r) * PITCH + ks * 16 + b4c) * 2;
                asm volatile("ldmatrix.sync.aligned.m8n8.x4.shared.b16 {%0,%1,%2,%3}, [%4];"
                    : "=r"(b0), "=r"(b1), "=r"(b2), "=r"(b3) : "r"(ad));
                MMA_F16(s[n],     aq[ks], b0, b1);
                MMA_F16(s[n + 1], aq[ks], b2, b3);
            }
        }

        // ---- exp in f16x2 (scores pre-scaled to log2 domain via Wq fold) ----
        uint32_t pl[8], pr[8];
        #pragma unroll
        for (int n = 0; n < 8; ++n) {
            float a0 = s[n][0];
            float a1 = s[n][1];
            float a2 = s[n][2];
            float a3 = s[n][3];
            if (t >= 2 * g) {
                const int cb = j0 + n * 8 + cql;
                if (cb     > r0g) a0 = -60000.f;
                if (cb + 1 > r0g) a1 = -60000.f;
                if (cb     > r1g) a2 = -60000.f;
                if (cb + 1 > r1g) a3 = -60000.f;
            }
            uint32_t i0, i1;
            asm("cvt.rn.f16x2.f32 %0, %1, %2;" : "=r"(i0) : "f"(a1), "f"(a0));
            asm("cvt.rn.f16x2.f32 %0, %1, %2;" : "=r"(i1) : "f"(a3), "f"(a2));
            asm("ex2.approx.f16x2 %0, %1;" : "=r"(pl[n]) : "r"(i0));
            asm("ex2.approx.f16x2 %0, %1;" : "=r"(pr[n]) : "r"(i1));
        }

        // ---- l += P x ones (tensor pipe), then O += P V ----
        #pragma unroll
        for (int kk = 0; kk < 4; ++kk) {
            uint32_t ap[4] = {pl[2*kk], pr[2*kk], pl[2*kk+1], pr[2*kk+1]};
            MMA_F16(lacc, ap, ONE2, ONE2);
        }
        #pragma unroll
        for (int hn = 0; hn < 8; hn += 2) {
            #pragma unroll
            for (int kk = 0; kk < 4; ++kk) {
                uint32_t b0, b1, b2, b3;
                uint32_t ad = vbase + (uint32_t)((hn * 8 + b4r) * PITCH + kk * 16 + b4c) * 2;
                asm volatile("ldmatrix.sync.aligned.m8n8.x4.shared.b16 {%0,%1,%2,%3}, [%4];"
                    : "=r"(b0), "=r"(b1), "=r"(b2), "=r"(b3) : "r"(ad));
                uint32_t ap[4] = {pl[2*kk], pr[2*kk], pl[2*kk+1], pr[2*kk+1]};
                MMA_F16(o[hn],     ap, b0, b1);
                MMA_F16(o[hn + 1], ap, b2, b3);
            }
        }

        if (t + 1 < t1) CP_WAIT0();
        __syncthreads();
    }

    // ---- epilogue ----
    if (nc == 1) {
        // single-chunk group: lacc holds complete row sums -> write out directly
        const float inv0 = 1.0f / lacc[0];
        const float inv1 = 1.0f / lacc[2];
        float* o0 = out + ((size_t)b * TT + r0g) * HH + cql;
        float* o1 = out + ((size_t)b * TT + r1g) * HH + cql;
        #pragma unroll
        for (int hn = 0; hn < 8; ++hn) {
            *(float2*)(o0 + hn * 8) = make_float2(o[hn][0] * inv0, o[hn][1] * inv0);
            *(float2*)(o1 + hn * 8) = make_float2(o[hn][2] * inv1, o[hn][3] * inv1);
        }
        return;
    }

    // multi-chunk: store fp16 partials + l
    const int item = b * NCHUNK + (int)blockIdx.x;
    if ((lane & 3) == 0) {
        g_pl[(size_t)item * 128 + lr0] = lacc[0];
        g_pl[(size_t)item * 128 + lr1] = lacc[2];
    }
    {
        __half* po = g_po + (size_t)item * (128 * 64);
        __half* p0 = po + lr0 * 64 + cql;
        __half* p1 = po + lr1 * 64 + cql;
        #pragma unroll
        for (int hn = 0; hn < 8; ++hn) {
            *(__half2*)(p0 + hn * 8) = __floats2half2_rn(o[hn][0], o[hn][1]);
            *(__half2*)(p1 + hn * 8) = __floats2half2_rn(o[hn][2], o[hn][3]);
        }
    }
    __threadfence();
    __syncthreads();

    __shared__ int s_old;
    if (tid == 0) s_old = atomicAdd(&g_cnt[b * 32 + g], 1);
    __syncthreads();
    if (s_old != nc - 1) return;

    // last finisher: reduce all chunks of this group and normalize
    __threadfence();
    const int base = b * NCHUNK + ((int)blockIdx.x - cch);
    const int r  = tid >> 1;                 // 0..127
    const int c0 = (tid & 1) * 32;           // 32 halves per thread

    float l = 0.f;
    #pragma unroll 1
    for (int c = 0; c < nc; ++c) l += g_pl[(size_t)(base + c) * 128 + r];
    const float inv = 1.0f / l;

    float acc[32];
    #pragma unroll
    for (int j = 0; j < 32; ++j) acc[j] = 0.f;
    #pragma unroll 1
    for (int c = 0; c < nc; ++c) {
        const __half* p = g_po + (size_t)(base + c) * (128 * 64) + r * 64 + c0;
        #pragma unroll
        for (int q = 0; q < 4; ++q) {
            uint4 v = *(const uint4*)(p + q * 8);
            float2 f0 = __half22float2(*(const __half2*)&v.x);
            float2 f1 = __half22float2(*(const __half2*)&v.y);
            float2 f2 = __half22float2(*(const __half2*)&v.z);
            float2 f3 = __half22float2(*(const __half2*)&v.w);
            acc[q*8+0] += f0.x; acc[q*8+1] += f0.y;
            acc[q*8+2] += f1.x; acc[q*8+3] += f1.y;
            acc[q*8+4] += f2.x; acc[q*8+5] += f2.y;
            acc[q*8+6] += f3.x; acc[q*8+7] += f3.y;
        }
    }
    float* orow = out + ((size_t)b * TT + qi0 + r) * HH + c0;
    #pragma unroll
    for (int q = 0; q < 8; ++q) {
        float4 w = make_float4(acc[q*4+0] * inv, acc[q*4+1] * inv,
                               acc[q*4+2] * inv, acc[q*4+3] * inv);
        *(float4*)(orow + q * 4) = w;
    }

    // reset counter for the next graph replay (deterministic)
    if (tid == 0) g_cnt[b * 32 + g] = 0;
}

// ---------------------------------------------------------------------------
extern "C" void kernel_launch(void* const* d_in, const int* in_sizes, int n_in,
                              void* d_out, int out_size)
{
    (void)in_sizes; (void)n_in; (void)out_size;
    const float* x  = (const float*)d_in[0];
    const float* Wq = (const float*)d_in[1];
    const float* Wk = (const float*)d_in[2];
    const float* Wv = (const float*)d_in[3];
    float* out = (float*)d_out;

    cudaFuncSetAttribute(proj_mma, cudaFuncAttributeMaxDynamicSharedMemorySize, PROJ_SMEM);
    cudaFuncSetAttribute(flash_chunk, cudaFuncAttributeMaxDynamicSharedMemorySize, FLASH_SMEM);

    conv_w<<<48, 256>>>(Wq, Wk, Wv);
    proj_mma<<<(BB * TT) / 64, 256, PROJ_SMEM>>>(x);
    flash_chunk<<<dim3(NCHUNK, BB), 256, FLASH_SMEM>>>(out);
}

// round 16
// speedup vs baseline: 1.0453x; 1.0453x over previous
#include <cuda_runtime.h>
#include <cuda_fp16.h>
#include <cstdint>

#define BB 8
#define TT 4096
#define DD 512
#define HH 64

// device-global scratch (allocation-free)
__device__ __half g_qh[BB * TT * HH];            // [b*T + t][h] (pre-scaled by scale*log2e)
__device__ __half g_kh[BB * TT * HH];            // [b*T + t][h]
__device__ __half g_vt[BB * HH * TT];            // [b][h][t]  (V transposed)
__device__ __half g_w3h[DD * 192];               // fp16 W interleaved [k][m*64+n]
#define NCHUNK 144                               // key-chunks per batch
__device__ __half g_po[BB * NCHUNK * 128 * 64];  // partial O (unnormalized, fp16)
__device__ float  g_pl[BB * NCHUNK * 128];       // partial l

__device__ __forceinline__ uint32_t smem_to_u32(const void* p) {
    uint32_t a;
    asm("{ .reg .u64 t; cvta.to.shared.u64 t, %1; cvt.u32.u64 %0, t; }" : "=r"(a) : "l"(p));
    return a;
}
#define CP_ASYNC16(dst, src) \
    asm volatile("cp.async.cg.shared.global [%0], [%1], 16;" :: "r"(dst), "l"(src))
#define CP_COMMIT() asm volatile("cp.async.commit_group;")
#define CP_WAIT0()  asm volatile("cp.async.wait_group 0;" ::: "memory")

#define MMA_F16(d, a, b0, b1) \
    asm volatile("mma.sync.aligned.m16n8k16.row.col.f32.f16.f16.f32 " \
        "{%0,%1,%2,%3}, {%4,%5,%6,%7}, {%8,%9}, {%0,%1,%2,%3};" \
        : "+f"((d)[0]), "+f"((d)[1]), "+f"((d)[2]), "+f"((d)[3]) \
        : "r"((a)[0]), "r"((a)[1]), "r"((a)[2]), "r"((a)[3]), "r"(b0), "r"(b1))

// scale * log2(e), folded into Wq
#define SCL2E 0.06376259339187951f

// ---------------------------------------------------------------------------
// W pre-conversion: fp32 -> fp16, interleaved [k][m*64+n]; Wq scaled by SCL2E
// 96 CTAs x 256 threads, 4 halves/thread (latency-bound kernel: max parallelism)
// ---------------------------------------------------------------------------
__global__ __launch_bounds__(256) void conv_w(
    const float* __restrict__ Wq, const float* __restrict__ Wk, const float* __restrict__ Wv)
{
    int gid = blockIdx.x * 256 + threadIdx.x;      // 24576 threads, 4 halves each
    int col = (gid * 4) % 192;
    int k   = (gid * 4) / 192;
    int m   = col / 64;
    int n   = col % 64;
    const float* W = (m == 0) ? Wq : ((m == 1) ? Wk : Wv);
    const float sc = (m == 0) ? SCL2E : 1.0f;
    float4 a = *(const float4*)&W[(size_t)k * HH + n];
    __half2 h0 = __floats2half2_rn(a.x * sc, a.y * sc);
    __half2 h1 = __floats2half2_rn(a.z * sc, a.w * sc);
    uint2 o;
    o.x = *(uint32_t*)&h0; o.y = *(uint32_t*)&h1;
    *(uint2*)&g_w3h[(size_t)k * 192 + col] = o;
}

// ---------------------------------------------------------------------------
// Kernel 1: QKV projection. 64-row CTA tiles, fp32 X loaded direct via LDG
// register prefetch (cvt->STS), W fp16 cp.async double-buffered.
// ---------------------------------------------------------------------------
#define XP 72    // X tile pitch (halves)
#define WP 200   // W tile pitch (halves)
#define VP 72    // V staging pitch (halves)
#define PX0 0
#define PX1 9216
#define PW0 18432
#define PW1 44032
#define PROJ_SMEM 69632

__device__ __forceinline__ void w_cp(uint32_t smb, int kc, int buf, int tid)
{
    const __half* wsrc = g_w3h + (size_t)(kc * 64) * 192;
    const uint32_t wb = smb + (buf ? PW1 : PW0);
    #pragma unroll
    for (int it = 0; it < 6; ++it) {
        int idx = tid + it * 256;                  // 0..1535
        int r = idx / 24, c = idx % 24;
        CP_ASYNC16(wb + (uint32_t)(r * (WP * 2) + c * 16), wsrc + (size_t)r * 192 + c * 8);
    }
}

__global__ __launch_bounds__(256, 2) void proj_mma(const float* __restrict__ x)
{
    extern __shared__ __align__(16) char psm[];
    const uint32_t smb = smem_to_u32(psm);
    __half* Vst = (__half*)psm;                    // reuses X buffers after mainloop

    const int tid  = threadIdx.x;
    const int warp = tid >> 5;
    const int lane = tid & 31;
    const int wm   = warp >> 2;                    // 0..1 (32 rows each)
    const int wn   = warp & 3;                     // 0..3 (48 cols each)
    const int row0 = blockIdx.x * 64;

    float acc[2][6][4];
    #pragma unroll
    for (int mt = 0; mt < 2; ++mt)
        #pragma unroll
        for (int nt = 0; nt < 6; ++nt)
            acc[mt][nt][0] = acc[mt][nt][1] = acc[mt][nt][2] = acc[mt][nt][3] = 0.f;

    float4 xr[4];
    #pragma unroll
    for (int it = 0; it < 4; ++it) {
        int idx = tid + it * 256;
        int r = idx >> 4, c4 = (idx & 15) * 4;
        xr[it] = *(const float4*)&x[(size_t)(row0 + r) * DD + 0 * 64 + c4];
    }
    {
        __half* Xb = (__half*)(psm + PX0);
        #pragma unroll
        for (int it = 0; it < 4; ++it) {
            int idx = tid + it * 256;
            int r = idx >> 4, c4 = (idx & 15) * 4;
            __half2 h0 = __floats2half2_rn(xr[it].x, xr[it].y);
            __half2 h1 = __floats2half2_rn(xr[it].z, xr[it].w);
            uint2 pk; pk.x = *(uint32_t*)&h0; pk.y = *(uint32_t*)&h1;
            *(uint2*)&Xb[r * XP + c4] = pk;
        }
    }
    w_cp(smb, 0, 0, tid);
    CP_COMMIT();
    #pragma unroll
    for (int it = 0; it < 4; ++it) {
        int idx = tid + it * 256;
        int r = idx >> 4, c4 = (idx & 15) * 4;
        xr[it] = *(const float4*)&x[(size_t)(row0 + r) * DD + 1 * 64 + c4];
    }
    CP_WAIT0();
    __syncthreads();

    for (int kc = 0; kc < 8; ++kc) {
        if (kc < 7) { w_cp(smb, kc + 1, (kc + 1) & 1, tid); CP_COMMIT(); }

        const uint32_t xb = smb + ((kc & 1) ? PX1 : PX0);
        const uint32_t wb = smb + ((kc & 1) ? PW1 : PW0);

        #pragma unroll
        for (int ks = 0; ks < 4; ++ks) {
            uint32_t a[2][4];
            #pragma unroll
            for (int mt = 0; mt < 2; ++mt) {
                int row = wm * 32 + mt * 16 + (lane & 7) + ((lane >> 3) & 1) * 8;
                int col = ks * 16 + ((lane >> 4) << 3);
                uint32_t ad = xb + (uint32_t)(row * XP + col) * 2;
                asm volatile("ldmatrix.sync.aligned.m8n8.x4.shared.b16 {%0,%1,%2,%3}, [%4];"
                    : "=r"(a[mt][0]), "=r"(a[mt][1]), "=r"(a[mt][2]), "=r"(a[mt][3])
                    : "r"(ad));
            }
            #pragma unroll
            for (int nt = 0; nt < 6; ++nt) {
                uint32_t b0, b1;
                uint32_t ad = wb +
                    (uint32_t)((ks * 16 + (lane & 15)) * WP + wn * 48 + nt * 8) * 2;
                asm volatile("ldmatrix.sync.aligned.m8n8.x2.trans.shared.b16 {%0,%1}, [%2];"
                    : "=r"(b0), "=r"(b1) : "r"(ad));
                #pragma unroll
                for (int mt = 0; mt < 2; ++mt)
                    MMA_F16(acc[mt][nt], a[mt], b0, b1);
            }
        }

        if (kc < 7) {
            __half* Xb = (__half*)(psm + (((kc + 1) & 1) ? PX1 : PX0));
            #pragma unroll
            for (int it = 0; it < 4; ++it) {
                int idx = tid + it * 256;
                int r = idx >> 4, c4 = (idx & 15) * 4;
                __half2 h0 = __floats2half2_rn(xr[it].x, xr[it].y);
                __half2 h1 = __floats2half2_rn(xr[it].z, xr[it].w);
                uint2 pk; pk.x = *(uint32_t*)&h0; pk.y = *(uint32_t*)&h1;
                *(uint2*)&Xb[r * XP + c4] = pk;
            }
            if (kc < 6) {
                #pragma unroll
                for (int it = 0; it < 4; ++it) {
                    int idx = tid + it * 256;
                    int r = idx >> 4, c4 = (idx & 15) * 4;
                    xr[it] = *(const float4*)&x[(size_t)(row0 + r) * DD + (kc + 2) * 64 + c4];
                }
            }
            CP_WAIT0();
        }
        __syncthreads();
    }

    // ---- store Q/K direct; stage V for transposed coalesced write ----
    const int rA = lane >> 2;
    const int cA = (lane & 3) * 2;
    #pragma unroll
    for (int mt = 0; mt < 2; ++mt) {
        #pragma unroll
        for (int nt = 0; nt < 6; ++nt) {
            const int n0 = wn * 48 + nt * 8 + cA;
            const int r  = wm * 32 + mt * 16 + rA;
            if (n0 < 128) {
                __half* dst = (n0 < 64) ? g_qh : g_kh;
                const int nn = n0 & 63;
                *(__half2*)&dst[(size_t)(row0 + r) * HH + nn] =
                    __floats2half2_rn(acc[mt][nt][0], acc[mt][nt][1]);
                *(__half2*)&dst[(size_t)(row0 + r + 8) * HH + nn] =
                    __floats2half2_rn(acc[mt][nt][2], acc[mt][nt][3]);
            } else {
                const int h = n0 - 128;
                Vst[h * VP + r]           = __float2half(acc[mt][nt][0]);
                Vst[(h + 1) * VP + r]     = __float2half(acc[mt][nt][1]);
                Vst[h * VP + r + 8]       = __float2half(acc[mt][nt][2]);
                Vst[(h + 1) * VP + r + 8] = __float2half(acc[mt][nt][3]);
            }
        }
    }
    __syncthreads();

    const int b  = row0 >> 12;
    const int t0 = row0 & (TT - 1);
    #pragma unroll
    for (int it = 0; it < 2; ++it) {
        int idx = tid + it * 256;                  // 0..511
        int h = idx >> 3, tc = (idx & 7) * 8;
        uint4 v = *(uint4*)&Vst[h * VP + tc];
        *(uint4*)&g_vt[((size_t)b * HH + h) * TT + t0 + tc] = v;
    }
}

// ---------------------------------------------------------------------------
// Kernel 2: split-K flash chunks (8 warps, 16 q-rows per warp).
// exp in f16x2 on MUFU; l via P x ones MMA; scores pre-scaled in log2 domain.
// ---------------------------------------------------------------------------
#define PITCH 72
#define QOFF  0
#define KOFF0 18432
#define KOFF1 27648
#define VOFF0 36864
#define VOFF1 46080
#define FLASH_SMEM 55296

__device__ __forceinline__ void kv_cp(uint32_t smb, const __half* kg, const __half* vtg,
                                      int j0, int buf, int tid)
{
    const uint32_t kb = smb + (buf ? KOFF1 : KOFF0);
    const uint32_t vb = smb + (buf ? VOFF1 : VOFF0);
    #pragma unroll
    for (int it = 0; it < 2; ++it) {
        int idx = tid + it * 256;
        int r = idx >> 3, c = idx & 7;
        CP_ASYNC16(kb + (uint32_t)(r * (PITCH * 2) + c * 16),
                   kg + (size_t)(j0 + r) * HH + c * 8);
        CP_ASYNC16(vb + (uint32_t)(r * (PITCH * 2) + c * 16),
                   vtg + (size_t)r * TT + j0 + c * 8);
    }
}

__global__ __launch_bounds__(256, 2) void flash_chunk(int dummy)
{
    extern __shared__ __align__(16) char sm[];
    const uint32_t smb = smem_to_u32(sm);

    const int tid  = threadIdx.x;
    const int warp = tid >> 5;
    const int lane = tid & 31;
    const int b    = blockIdx.y;

    // decode work item -> (g, c)
    int g = 0, cch = 0;
    {
        int it = blockIdx.x, off = 0;
        #pragma unroll 1
        for (int gg = 0; gg < 32; ++gg) {
            int cg = (2 * gg + 9) >> 3;
            if (it < off + cg) { g = gg; cch = it - off; break; }
            off += cg;
        }
    }
    const int qi0 = g * 128;
    const int t0  = cch * 8;
    const int t1  = min(t0 + 8, 2 * g + 2);

    const __half* qg  = g_qh + ((size_t)b * TT + qi0) * HH;
    const __half* kg  = g_kh + (size_t)b * TT * HH;
    const __half* vtg = g_vt + (size_t)b * HH * TT;

    // prologue: Q + first K/V tile
    #pragma unroll
    for (int it = 0; it < 4; ++it) {
        int idx = tid + it * 256;
        int r = idx >> 3, c = idx & 7;
        CP_ASYNC16(smb + QOFF + (uint32_t)(r * (PITCH * 2) + c * 16),
                   qg + (size_t)r * HH + c * 8);
    }
    kv_cp(smb, kg, vtg, t0 * 64, t0 & 1, tid);
    CP_COMMIT();
    CP_WAIT0();
    __syncthreads();

    // Q A-fragments
    const int mrow = warp * 16;
    uint32_t aq[4][4];
    {
        int row = mrow + (lane & 7) + ((lane >> 3) & 1) * 8;
        int col = ((lane >> 4) << 3);
        #pragma unroll
        for (int ks = 0; ks < 4; ++ks) {
            uint32_t ad = smb + QOFF + (uint32_t)(row * PITCH + ks * 16 + col) * 2;
            asm volatile("ldmatrix.sync.aligned.m8n8.x4.shared.b16 {%0,%1,%2,%3}, [%4];"
                : "=r"(aq[ks][0]), "=r"(aq[ks][1]), "=r"(aq[ks][2]), "=r"(aq[ks][3])
                : "r"(ad));
        }
    }

    const int lr0 = mrow + (lane >> 2);           // local rows
    const int lr1 = lr0 + 8;
    const int r0g = qi0 + lr0;                    // global rows (for mask)
    const int r1g = r0g + 8;
    const int cql = (lane & 3) * 2;

    float o[8][4];
    #pragma unroll
    for (int n = 0; n < 8; ++n)
        #pragma unroll
        for (int i = 0; i < 4; ++i) o[n][i] = 0.f;
    float lacc[4] = {0.f, 0.f, 0.f, 0.f};         // l via P x ones MMA
    const uint32_t ONE2 = 0x3C003C00u;            // half2(1.0, 1.0)

    const int b4r = ((lane >> 4) << 3) + (lane & 7);
    const int b4c = ((lane >> 3) & 1) * 8;

    for (int t = t0; t < t1; ++t) {
        if (t + 1 < t1) { kv_cp(smb, kg, vtg, (t + 1) * 64, (t + 1) & 1, tid); CP_COMMIT(); }

        const uint32_t kbase = smb + ((t & 1) ? KOFF1 : KOFF0);
        const uint32_t vbase = smb + ((t & 1) ? VOFF1 : VOFF0);
        const int j0 = t * 64;

        // ---- S = Q K^T (x4 B loads: 2 j-tiles per ldmatrix) ----
        float s[8][4];
        #pragma unroll
        for (int n = 0; n < 8; n += 2) {
            s[n][0] = s[n][1] = s[n][2] = s[n][3] = 0.f;
            s[n+1][0] = s[n+1][1] = s[n+1][2] = s[n+1][3] = 0.f;
            #pragma unroll
            for (int ks = 0; ks < 4; ++ks) {
                uint32_t b0, b1, b2, b3;
                uint32_t ad = kbase + (uint32_t)((n * 8 + b4r) * PITCH + ks * 16 + b4c) * 2;
                asm volatile("ldmatrix.sync.aligned.m8n8.x4.shared.b16 {%0,%1,%2,%3}, [%4];"
                    : "=r"(b0), "=r"(b1), "=r"(b2), "=r"(b3) : "r"(ad));
                MMA_F16(s[n],     aq[ks], b0, b1);
                MMA_F16(s[n + 1], aq[ks], b2, b3);
            }
        }

        // ---- exp in f16x2 (scores pre-scaled to log2 domain via Wq fold) ----
        uint32_t pl[8], pr[8];
        #pragma unroll
        for (int n = 0; n < 8; ++n) {
            float a0 = s[n][0];
            float a1 = s[n][1];
            float a2 = s[n][2];
            float a3 = s[n][3];
            if (t >= 2 * g) {
                const int cb = j0 + n * 8 + cql;
                if (cb     > r0g) a0 = -60000.f;
                if (cb + 1 > r0g) a1 = -60000.f;
                if (cb     > r1g) a2 = -60000.f;
                if (cb + 1 > r1g) a3 = -60000.f;
            }
            uint32_t i0, i1;
            asm("cvt.rn.f16x2.f32 %0, %1, %2;" : "=r"(i0) : "f"(a1), "f"(a0));
            asm("cvt.rn.f16x2.f32 %0, %1, %2;" : "=r"(i1) : "f"(a3), "f"(a2));
            asm("ex2.approx.f16x2 %0, %1;" : "=r"(pl[n]) : "r"(i0));
            asm("ex2.approx.f16x2 %0, %1;" : "=r"(pr[n]) : "r"(i1));
        }

        // ---- l += P x ones (tensor pipe), then O += P V ----
        #pragma unroll
        for (int kk = 0; kk < 4; ++kk) {
            uint32_t ap[4] = {pl[2*kk], pr[2*kk], pl[2*kk+1], pr[2*kk+1]};
            MMA_F16(lacc, ap, ONE2, ONE2);
        }
        #pragma unroll
        for (int hn = 0; hn < 8; hn += 2) {
            #pragma unroll
            for (int kk = 0; kk < 4; ++kk) {
                uint32_t b0, b1, b2, b3;
                uint32_t ad = vbase + (uint32_t)((hn * 8 + b4r) * PITCH + kk * 16 + b4c) * 2;
                asm volatile("ldmatrix.sync.aligned.m8n8.x4.shared.b16 {%0,%1,%2,%3}, [%4];"
                    : "=r"(b0), "=r"(b1), "=r"(b2), "=r"(b3) : "r"(ad));
                uint32_t ap[4] = {pl[2*kk], pr[2*kk], pl[2*kk+1], pr[2*kk+1]};
                MMA_F16(o[hn],     ap, b0, b1);
                MMA_F16(o[hn + 1], ap, b2, b3);
            }
        }

        if (t + 1 < t1) CP_WAIT0();
        __syncthreads();
    }

    // ---- epilogue: l already reduced by the ones-MMA; store fp16 partials ----
    const int item = b * NCHUNK + (int)blockIdx.x;
    if ((lane & 3) == 0) {
        g_pl[(size_t)item * 128 + lr0] = lacc[0];
        g_pl[(size_t)item * 128 + lr1] = lacc[2];
    }
    __half* po = g_po + (size_t)item * (128 * 64);
    __half* p0 = po + lr0 * 64 + cql;
    __half* p1 = po + lr1 * 64 + cql;
    #pragma unroll
    for (int hn = 0; hn < 8; ++hn) {
        *(__half2*)(p0 + hn * 8) = __floats2half2_rn(o[hn][0], o[hn][1]);
        *(__half2*)(p1 + hn * 8) = __floats2half2_rn(o[hn][2], o[hn][3]);
    }
}

// ---------------------------------------------------------------------------
// Kernel 3: combine fp16 partials and normalize. CTA owns 16 q-rows; 2048 CTAs
// total, heavy groups (large nc) scheduled first for balanced tail.
// ---------------------------------------------------------------------------
__global__ __launch_bounds__(128) void combine_kernel(float* __restrict__ out)
{
    const int bx = blockIdx.x;
    const int g  = 31 - (bx >> 3);                 // heavy-first
    const int rc = bx & 7;
    const int b  = blockIdx.y;

    int off = 0;
    #pragma unroll 1
    for (int gg = 0; gg < 32; ++gg) { if (gg < g) off += (2 * gg + 9) >> 3; }
    const int nc   = (2 * g + 9) >> 3;
    const int base = b * NCHUNK + off;

    const int tid = threadIdx.x;
    const int r   = rc * 16 + (tid >> 3);          // q row within the 128-block
    const int c0  = (tid & 7) * 8;                 // 8 halves per thread

    float lv[9];
    uint4 pv[9];
    #pragma unroll
    for (int c = 0; c < 9; ++c) {
        if (c < nc) {
            lv[c] = g_pl[(size_t)(base + c) * 128 + r];
            pv[c] = *(const uint4*)(g_po + (size_t)(base + c) * (128 * 64) + r * 64 + c0);
        }
    }

    float l = 0.f;
    float acc[8];
    #pragma unroll
    for (int j = 0; j < 8; ++j) acc[j] = 0.f;
    #pragma unroll
    for (int c = 0; c < 9; ++c) {
        if (c < nc) {
            l += lv[c];
            float2 f0 = __half22float2(*(const __half2*)&pv[c].x);
            float2 f1 = __half22float2(*(const __half2*)&pv[c].y);
            float2 f2 = __half22float2(*(const __half2*)&pv[c].z);
            float2 f3 = __half22float2(*(const __half2*)&pv[c].w);
            acc[0] += f0.x; acc[1] += f0.y;
            acc[2] += f1.x; acc[3] += f1.y;
            acc[4] += f2.x; acc[5] += f2.y;
            acc[6] += f3.x; acc[7] += f3.y;
        }
    }
    const float inv = 1.0f / l;
    float* orow = out + ((size_t)b * TT + g * 128 + r) * HH + c0;
    float4 w0 = make_float4(acc[0] * inv, acc[1] * inv, acc[2] * inv, acc[3] * inv);
    float4 w1 = make_float4(acc[4] * inv, acc[5] * inv, acc[6] * inv, acc[7] * inv);
    *(float4*)(orow)     = w0;
    *(float4*)(orow + 4) = w1;
}

// ---------------------------------------------------------------------------
extern "C" void kernel_launch(void* const* d_in, const int* in_sizes, int n_in,
                              void* d_out, int out_size)
{
    (void)in_sizes; (void)n_in; (void)out_size;
    const float* x  = (const float*)d_in[0];
    const float* Wq = (const float*)d_in[1];
    const float* Wk = (const float*)d_in[2];
    const float* Wv = (const float*)d_in[3];
    float* out = (float*)d_out;

    cudaFuncSetAttribute(proj_mma, cudaFuncAttributeMaxDynamicSharedMemorySize, PROJ_SMEM);
    cudaFuncSetAttribute(flash_chunk, cudaFuncAttributeMaxDynamicSharedMemorySize, FLASH_SMEM);

    conv_w<<<96, 256>>>(Wq, Wk, Wv);
    proj_mma<<<(BB * TT) / 64, 256, PROJ_SMEM>>>(x);
    flash_chunk<<<dim3(NCHUNK, BB), 256, FLASH_SMEM>>>(0);
    combine_kernel<<<dim3(256, BB), 128>>>(out);
}

// round 17
// speedup vs baseline: 1.0622x; 1.0162x over previous
#include <cuda_runtime.h>
#include <cuda_fp16.h>
#include <cstdint>

#define BB 8
#define TT 4096
#define DD 512
#define HH 64

// device-global scratch (allocation-free)
__device__ __half g_qh[BB * TT * HH];            // [b*T + t][h] (pre-scaled by scale*log2e)
__device__ __half g_kh[BB * TT * HH];            // [b*T + t][h]
__device__ __half g_vt[BB * HH * TT];            // [b][h][t]  (V transposed)
__device__ __half g_w3h[DD * 192];               // fp16 W interleaved [k][m*64+n]
#define NCHUNK 144                               // key-chunks per batch
__device__ __half g_po[BB * NCHUNK * 128 * 64];  // partial O (unnormalized, fp16)
__device__ float  g_pl[BB * NCHUNK * 128];       // partial l

__device__ __forceinline__ uint32_t smem_to_u32(const void* p) {
    uint32_t a;
    asm("{ .reg .u64 t; cvta.to.shared.u64 t, %1; cvt.u32.u64 %0, t; }" : "=r"(a) : "l"(p));
    return a;
}
#define CP_ASYNC16(dst, src) \
    asm volatile("cp.async.cg.shared.global [%0], [%1], 16;" :: "r"(dst), "l"(src))
#define CP_COMMIT() asm volatile("cp.async.commit_group;")
#define CP_WAIT0()  asm volatile("cp.async.wait_group 0;" ::: "memory")

#define MMA_F16(d, a, b0, b1) \
    asm volatile("mma.sync.aligned.m16n8k16.row.col.f32.f16.f16.f32 " \
        "{%0,%1,%2,%3}, {%4,%5,%6,%7}, {%8,%9}, {%0,%1,%2,%3};" \
        : "+f"((d)[0]), "+f"((d)[1]), "+f"((d)[2]), "+f"((d)[3]) \
        : "r"((a)[0]), "r"((a)[1]), "r"((a)[2]), "r"((a)[3]), "r"(b0), "r"(b1))

// scale * log2(e), folded into Wq
#define SCL2E 0.06376259339187951f

// ---------------------------------------------------------------------------
// W pre-conversion: fp32 -> fp16, interleaved [k][m*64+n]; Wq scaled by SCL2E
// ---------------------------------------------------------------------------
__global__ __launch_bounds__(256) void conv_w(
    const float* __restrict__ Wq, const float* __restrict__ Wk, const float* __restrict__ Wv)
{
    int gid = blockIdx.x * 256 + threadIdx.x;      // 24576 threads, 4 halves each
    int col = (gid * 4) % 192;
    int k   = (gid * 4) / 192;
    int m   = col / 64;
    int n   = col % 64;
    const float* W = (m == 0) ? Wq : ((m == 1) ? Wk : Wv);
    const float sc = (m == 0) ? SCL2E : 1.0f;
    float4 a = *(const float4*)&W[(size_t)k * HH + n];
    __half2 h0 = __floats2half2_rn(a.x * sc, a.y * sc);
    __half2 h1 = __floats2half2_rn(a.z * sc, a.w * sc);
    uint2 o;
    o.x = *(uint32_t*)&h0; o.y = *(uint32_t*)&h1;
    *(uint2*)&g_w3h[(size_t)k * 192 + col] = o;
}

// ---------------------------------------------------------------------------
// Kernel 1: QKV projection. 64-row CTA tiles, fp32 X loaded direct via LDG
// register prefetch (cvt->STS), W fp16 cp.async double-buffered.
// ---------------------------------------------------------------------------
#define XP 72    // X tile pitch (halves)
#define WP 200   // W tile pitch (halves)
#define VP 72    // V staging pitch (halves)
#define PX0 0
#define PX1 9216
#define PW0 18432
#define PW1 44032
#define PROJ_SMEM 69632

__device__ __forceinline__ void w_cp(uint32_t smb, int kc, int buf, int tid)
{
    const __half* wsrc = g_w3h + (size_t)(kc * 64) * 192;
    const uint32_t wb = smb + (buf ? PW1 : PW0);
    #pragma unroll
    for (int it = 0; it < 6; ++it) {
        int idx = tid + it * 256;                  // 0..1535
        int r = idx / 24, c = idx % 24;
        CP_ASYNC16(wb + (uint32_t)(r * (WP * 2) + c * 16), wsrc + (size_t)r * 192 + c * 8);
    }
}

__global__ __launch_bounds__(256, 2) void proj_mma(const float* __restrict__ x)
{
    extern __shared__ __align__(16) char psm[];
    const uint32_t smb = smem_to_u32(psm);
    __half* Vst = (__half*)psm;                    // reuses X buffers after mainloop

    const int tid  = threadIdx.x;
    const int warp = tid >> 5;
    const int lane = tid & 31;
    const int wm   = warp >> 2;                    // 0..1 (32 rows each)
    const int wn   = warp & 3;                     // 0..3 (48 cols each)
    const int row0 = blockIdx.x * 64;

    float acc[2][6][4];
    #pragma unroll
    for (int mt = 0; mt < 2; ++mt)
        #pragma unroll
        for (int nt = 0; nt < 6; ++nt)
            acc[mt][nt][0] = acc[mt][nt][1] = acc[mt][nt][2] = acc[mt][nt][3] = 0.f;

    float4 xr[4];
    #pragma unroll
    for (int it = 0; it < 4; ++it) {
        int idx = tid + it * 256;
        int r = idx >> 4, c4 = (idx & 15) * 4;
        xr[it] = *(const float4*)&x[(size_t)(row0 + r) * DD + 0 * 64 + c4];
    }
    {
        __half* Xb = (__half*)(psm + PX0);
        #pragma unroll
        for (int it = 0; it < 4; ++it) {
            int idx = tid + it * 256;
            int r = idx >> 4, c4 = (idx & 15) * 4;
            __half2 h0 = __floats2half2_rn(xr[it].x, xr[it].y);
            __half2 h1 = __floats2half2_rn(xr[it].z, xr[it].w);
            uint2 pk; pk.x = *(uint32_t*)&h0; pk.y = *(uint32_t*)&h1;
            *(uint2*)&Xb[r * XP + c4] = pk;
        }
    }
    w_cp(smb, 0, 0, tid);
    CP_COMMIT();
    #pragma unroll
    for (int it = 0; it < 4; ++it) {
        int idx = tid + it * 256;
        int r = idx >> 4, c4 = (idx & 15) * 4;
        xr[it] = *(const float4*)&x[(size_t)(row0 + r) * DD + 1 * 64 + c4];
    }
    CP_WAIT0();
    __syncthreads();

    for (int kc = 0; kc < 8; ++kc) {
        if (kc < 7) { w_cp(smb, kc + 1, (kc + 1) & 1, tid); CP_COMMIT(); }

        const uint32_t xb = smb + ((kc & 1) ? PX1 : PX0);
        const uint32_t wb = smb + ((kc & 1) ? PW1 : PW0);

        #pragma unroll
        for (int ks = 0; ks < 4; ++ks) {
            uint32_t a[2][4];
            #pragma unroll
            for (int mt = 0; mt < 2; ++mt) {
                int row = wm * 32 + mt * 16 + (lane & 7) + ((lane >> 3) & 1) * 8;
                int col = ks * 16 + ((lane >> 4) << 3);
                uint32_t ad = xb + (uint32_t)(row * XP + col) * 2;
                asm volatile("ldmatrix.sync.aligned.m8n8.x4.shared.b16 {%0,%1,%2,%3}, [%4];"
                    : "=r"(a[mt][0]), "=r"(a[mt][1]), "=r"(a[mt][2]), "=r"(a[mt][3])
                    : "r"(ad));
            }
            #pragma unroll
            for (int nt = 0; nt < 6; ++nt) {
                uint32_t b0, b1;
                uint32_t ad = wb +
                    (uint32_t)((ks * 16 + (lane & 15)) * WP + wn * 48 + nt * 8) * 2;
                asm volatile("ldmatrix.sync.aligned.m8n8.x2.trans.shared.b16 {%0,%1}, [%2];"
                    : "=r"(b0), "=r"(b1) : "r"(ad));
                #pragma unroll
                for (int mt = 0; mt < 2; ++mt)
                    MMA_F16(acc[mt][nt], a[mt], b0, b1);
            }
        }

        if (kc < 7) {
            __half* Xb = (__half*)(psm + (((kc + 1) & 1) ? PX1 : PX0));
            #pragma unroll
            for (int it = 0; it < 4; ++it) {
                int idx = tid + it * 256;
                int r = idx >> 4, c4 = (idx & 15) * 4;
                __half2 h0 = __floats2half2_rn(xr[it].x, xr[it].y);
                __half2 h1 = __floats2half2_rn(xr[it].z, xr[it].w);
                uint2 pk; pk.x = *(uint32_t*)&h0; pk.y = *(uint32_t*)&h1;
                *(uint2*)&Xb[r * XP + c4] = pk;
            }
            if (kc < 6) {
                #pragma unroll
                for (int it = 0; it < 4; ++it) {
                    int idx = tid + it * 256;
                    int r = idx >> 4, c4 = (idx & 15) * 4;
                    xr[it] = *(const float4*)&x[(size_t)(row0 + r) * DD + (kc + 2) * 64 + c4];
                }
            }
            CP_WAIT0();
        }
        __syncthreads();
    }

    // ---- store Q/K direct; stage V for transposed coalesced write ----
    const int rA = lane >> 2;
    const int cA = (lane & 3) * 2;
    #pragma unroll
    for (int mt = 0; mt < 2; ++mt) {
        #pragma unroll
        for (int nt = 0; nt < 6; ++nt) {
            const int n0 = wn * 48 + nt * 8 + cA;
            const int r  = wm * 32 + mt * 16 + rA;
            if (n0 < 128) {
                __half* dst = (n0 < 64) ? g_qh : g_kh;
                const int nn = n0 & 63;
                *(__half2*)&dst[(size_t)(row0 + r) * HH + nn] =
                    __floats2half2_rn(acc[mt][nt][0], acc[mt][nt][1]);
                *(__half2*)&dst[(size_t)(row0 + r + 8) * HH + nn] =
                    __floats2half2_rn(acc[mt][nt][2], acc[mt][nt][3]);
            } else {
                const int h = n0 - 128;
                Vst[h * VP + r]           = __float2half(acc[mt][nt][0]);
                Vst[(h + 1) * VP + r]     = __float2half(acc[mt][nt][1]);
                Vst[h * VP + r + 8]       = __float2half(acc[mt][nt][2]);
                Vst[(h + 1) * VP + r + 8] = __float2half(acc[mt][nt][3]);
            }
        }
    }
    __syncthreads();

    const int b  = row0 >> 12;
    const int t0 = row0 & (TT - 1);
    #pragma unroll
    for (int it = 0; it < 2; ++it) {
        int idx = tid + it * 256;                  // 0..511
        int h = idx >> 3, tc = (idx & 7) * 8;
        uint4 v = *(uint4*)&Vst[h * VP + tc];
        *(uint4*)&g_vt[((size_t)b * HH + h) * TT + t0 + tc] = v;
    }
}

// ---------------------------------------------------------------------------
// Kernel 2: split-K flash chunks (8 warps, 16 q-rows per warp), heavy-first
// scheduling. nc==1 groups (g<=3) normalize and write out directly.
// ---------------------------------------------------------------------------
#define PITCH 72
#define QOFF  0
#define KOFF0 18432
#define KOFF1 27648
#define VOFF0 36864
#define VOFF1 46080
#define FLASH_SMEM 55296

__device__ __forceinline__ void kv_cp(uint32_t smb, const __half* kg, const __half* vtg,
                                      int j0, int buf, int tid)
{
    const uint32_t kb = smb + (buf ? KOFF1 : KOFF0);
    const uint32_t vb = smb + (buf ? VOFF1 : VOFF0);
    #pragma unroll
    for (int it = 0; it < 2; ++it) {
        int idx = tid + it * 256;
        int r = idx >> 3, c = idx & 7;
        CP_ASYNC16(kb + (uint32_t)(r * (PITCH * 2) + c * 16),
                   kg + (size_t)(j0 + r) * HH + c * 8);
        CP_ASYNC16(vb + (uint32_t)(r * (PITCH * 2) + c * 16),
                   vtg + (size_t)r * TT + j0 + c * 8);
    }
}

__global__ __launch_bounds__(256, 2) void flash_chunk(float* __restrict__ out)
{
    extern __shared__ __align__(16) char sm[];
    const uint32_t smb = smem_to_u32(sm);

    const int tid  = threadIdx.x;
    const int warp = tid >> 5;
    const int lane = tid & 31;
    const int b    = blockIdx.y;

    // decode work item -> (g, cch); heavy groups first (reversed index)
    int g = 0, cch = 0, off = 0;
    {
        int it = (int)(gridDim.x - 1 - blockIdx.x);
        #pragma unroll 1
        for (int gg = 0; gg < 32; ++gg) {
            int cg = (2 * gg + 9) >> 3;
            if (it < off + cg) { g = gg; cch = it - off; break; }
            off += cg;
        }
    }
    const int qi0 = g * 128;
    const int t0  = cch * 8;
    const int t1  = min(t0 + 8, 2 * g + 2);
    const int nc  = (2 * g + 9) >> 3;

    const __half* qg  = g_qh + ((size_t)b * TT + qi0) * HH;
    const __half* kg  = g_kh + (size_t)b * TT * HH;
    const __half* vtg = g_vt + (size_t)b * HH * TT;

    // prologue: Q + first K/V tile
    #pragma unroll
    for (int it = 0; it < 4; ++it) {
        int idx = tid + it * 256;
        int r = idx >> 3, c = idx & 7;
        CP_ASYNC16(smb + QOFF + (uint32_t)(r * (PITCH * 2) + c * 16),
                   qg + (size_t)r * HH + c * 8);
    }
    kv_cp(smb, kg, vtg, t0 * 64, t0 & 1, tid);
    CP_COMMIT();
    CP_WAIT0();
    __syncthreads();

    // Q A-fragments
    const int mrow = warp * 16;
    uint32_t aq[4][4];
    {
        int row = mrow + (lane & 7) + ((lane >> 3) & 1) * 8;
        int col = ((lane >> 4) << 3);
        #pragma unroll
        for (int ks = 0; ks < 4; ++ks) {
            uint32_t ad = smb + QOFF + (uint32_t)(row * PITCH + ks * 16 + col) * 2;
            asm volatile("ldmatrix.sync.aligned.m8n8.x4.shared.b16 {%0,%1,%2,%3}, [%4];"
                : "=r"(aq[ks][0]), "=r"(aq[ks][1]), "=r"(aq[ks][2]), "=r"(aq[ks][3])
                : "r"(ad));
        }
    }

    const int lr0 = mrow + (lane >> 2);           // local rows
    const int lr1 = lr0 + 8;
    const int r0g = qi0 + lr0;                    // global rows (for mask)
    const int r1g = r0g + 8;
    const int cql = (lane & 3) * 2;

    float o[8][4];
    #pragma unroll
    for (int n = 0; n < 8; ++n)
        #pragma unroll
        for (int i = 0; i < 4; ++i) o[n][i] = 0.f;
    float lacc[4] = {0.f, 0.f, 0.f, 0.f};         // l via P x ones MMA
    const uint32_t ONE2 = 0x3C003C00u;            // half2(1.0, 1.0)

    const int b4r = ((lane >> 4) << 3) + (lane & 7);
    const int b4c = ((lane >> 3) & 1) * 8;

    for (int t = t0; t < t1; ++t) {
        if (t + 1 < t1) { kv_cp(smb, kg, vtg, (t + 1) * 64, (t + 1) & 1, tid); CP_COMMIT(); }

        const uint32_t kbase = smb + ((t & 1) ? KOFF1 : KOFF0);
        const uint32_t vbase = smb + ((t & 1) ? VOFF1 : VOFF0);
        const int j0 = t * 64;

        // ---- S = Q K^T (x4 B loads: 2 j-tiles per ldmatrix) ----
        float s[8][4];
        #pragma unroll
        for (int n = 0; n < 8; n += 2) {
            s[n][0] = s[n][1] = s[n][2] = s[n][3] = 0.f;
            s[n+1][0] = s[n+1][1] = s[n+1][2] = s[n+1][3] = 0.f;
            #pragma unroll
            for (int ks = 0; ks < 4; ++ks) {
                uint32_t b0, b1, b2, b3;
                uint32_t ad = kbase + (uint32_t)((n * 8 + b4r) * PITCH + ks * 16 + b4c) * 2;
                asm volatile("ldmatrix.sync.aligned.m8n8.x4.shared.b16 {%0,%1,%2,%3}, [%4];"
                    : "=r"(b0), "=r"(b1), "=r"(b2), "=r"(b3) : "r"(ad));
                MMA_F16(s[n],     aq[ks], b0, b1);
                MMA_F16(s[n + 1], aq[ks], b2, b3);
            }
        }

        // ---- exp in f16x2 (scores pre-scaled to log2 domain via Wq fold) ----
        uint32_t pl[8], pr[8];
        #pragma unroll
        for (int n = 0; n < 8; ++n) {
            float a0 = s[n][0];
            float a1 = s[n][1];
            float a2 = s[n][2];
            float a3 = s[n][3];
            if (t >= 2 * g) {
                const int cb = j0 + n * 8 + cql;
                if (cb     > r0g) a0 = -60000.f;
                if (cb + 1 > r0g) a1 = -60000.f;
                if (cb     > r1g) a2 = -60000.f;
                if (cb + 1 > r1g) a3 = -60000.f;
            }
            uint32_t i0, i1;
            asm("cvt.rn.f16x2.f32 %0, %1, %2;" : "=r"(i0) : "f"(a1), "f"(a0));
            asm("cvt.rn.f16x2.f32 %0, %1, %2;" : "=r"(i1) : "f"(a3), "f"(a2));
            asm("ex2.approx.f16x2 %0, %1;" : "=r"(pl[n]) : "r"(i0));
            asm("ex2.approx.f16x2 %0, %1;" : "=r"(pr[n]) : "r"(i1));
        }

        // ---- l += P x ones (tensor pipe), then O += P V ----
        #pragma unroll
        for (int kk = 0; kk < 4; ++kk) {
            uint32_t ap[4] = {pl[2*kk], pr[2*kk], pl[2*kk+1], pr[2*kk+1]};
            MMA_F16(lacc, ap, ONE2, ONE2);
        }
        #pragma unroll
        for (int hn = 0; hn < 8; hn += 2) {
            #pragma unroll
            for (int kk = 0; kk < 4; ++kk) {
                uint32_t b0, b1, b2, b3;
                uint32_t ad = vbase + (uint32_t)((hn * 8 + b4r) * PITCH + kk * 16 + b4c) * 2;
                asm volatile("ldmatrix.sync.aligned.m8n8.x4.shared.b16 {%0,%1,%2,%3}, [%4];"
                    : "=r"(b0), "=r"(b1), "=r"(b2), "=r"(b3) : "r"(ad));
                uint32_t ap[4] = {pl[2*kk], pr[2*kk], pl[2*kk+1], pr[2*kk+1]};
                MMA_F16(o[hn],     ap, b0, b1);
                MMA_F16(o[hn + 1], ap, b2, b3);
            }
        }

        if (t + 1 < t1) { CP_WAIT0(); __syncthreads(); }
    }

    // ---- epilogue ----
    if (nc == 1) {
        // single-chunk group: lacc holds complete row sums -> write out directly
        const float inv0 = 1.0f / lacc[0];
        const float inv1 = 1.0f / lacc[2];
        float* o0 = out + ((size_t)b * TT + r0g) * HH + cql;
        float* o1 = out + ((size_t)b * TT + r1g) * HH + cql;
        #pragma unroll
        for (int hn = 0; hn < 8; ++hn) {
            *(float2*)(o0 + hn * 8) = make_float2(o[hn][0] * inv0, o[hn][1] * inv0);
            *(float2*)(o1 + hn * 8) = make_float2(o[hn][2] * inv1, o[hn][3] * inv1);
        }
        return;
    }

    // multi-chunk: store fp16 partials + l at LOGICAL chunk index (off + cch)
    const int item = b * NCHUNK + off + cch;
    if ((lane & 3) == 0) {
        g_pl[(size_t)item * 128 + lr0] = lacc[0];
        g_pl[(size_t)item * 128 + lr1] = lacc[2];
    }
    __half* po = g_po + (size_t)item * (128 * 64);
    __half* p0 = po + lr0 * 64 + cql;
    __half* p1 = po + lr1 * 64 + cql;
    #pragma unroll
    for (int hn = 0; hn < 8; ++hn) {
        *(__half2*)(p0 + hn * 8) = __floats2half2_rn(o[hn][0], o[hn][1]);
        *(__half2*)(p1 + hn * 8) = __floats2half2_rn(o[hn][2], o[hn][3]);
    }
}

// ---------------------------------------------------------------------------
// Kernel 3: combine fp16 partials for groups g=4..31 (nc>1), heavy-first.
// CTA owns 16 q-rows.
// ---------------------------------------------------------------------------
__global__ __launch_bounds__(128) void combine_kernel(float* __restrict__ out)
{
    const int bx = blockIdx.x;
    const int g  = 31 - (bx >> 3);                 // heavy-first; bx 0..223 -> g 31..4
    const int rc = bx & 7;
    const int b  = blockIdx.y;

    int off = 0;
    #pragma unroll 1
    for (int gg = 0; gg < 32; ++gg) { if (gg < g) off += (2 * gg + 9) >> 3; }
    const int nc   = (2 * g + 9) >> 3;
    const int base = b * NCHUNK + off;

    const int tid = threadIdx.x;
    const int r   = rc * 16 + (tid >> 3);          // q row within the 128-block
    const int c0  = (tid & 7) * 8;                 // 8 halves per thread

    float lv[9];
    uint4 pv[9];
    #pragma unroll
    for (int c = 0; c < 9; ++c) {
        if (c < nc) {
            lv[c] = g_pl[(size_t)(base + c) * 128 + r];
            pv[c] = *(const uint4*)(g_po + (size_t)(base + c) * (128 * 64) + r * 64 + c0);
        }
    }

    float l = 0.f;
    float acc[8];
    #pragma unroll
    for (int j = 0; j < 8; ++j) acc[j] = 0.f;
    #pragma unroll
    for (int c = 0; c < 9; ++c) {
        if (c < nc) {
            l += lv[c];
            float2 f0 = __half22float2(*(const __half2*)&pv[c].x);
            float2 f1 = __half22float2(*(const __half2*)&pv[c].y);
            float2 f2 = __half22float2(*(const __half2*)&pv[c].z);
            float2 f3 = __half22float2(*(const __half2*)&pv[c].w);
            acc[0] += f0.x; acc[1] += f0.y;
            acc[2] += f1.x; acc[3] += f1.y;
            acc[4] += f2.x; acc[5] += f2.y;
            acc[6] += f3.x; acc[7] += f3.y;
        }
    }
    const float inv = 1.0f / l;
    float* orow = out + ((size_t)b * TT + g * 128 + r) * HH + c0;
    float4 w0 = make_float4(acc[0] * inv, acc[1] * inv, acc[2] * inv, acc[3] * inv);
    float4 w1 = make_float4(acc[4] * inv, acc[5] * inv, acc[6] * inv, acc[7] * inv);
    *(float4*)(orow)     = w0;
    *(float4*)(orow + 4) = w1;
}

// ---------------------------------------------------------------------------
extern "C" void kernel_launch(void* const* d_in, const int* in_sizes, int n_in,
                              void* d_out, int out_size)
{
    (void)in_sizes; (void)n_in; (void)out_size;
    const float* x  = (const float*)d_in[0];
    const float* Wq = (const float*)d_in[1];
    const float* Wk = (const float*)d_in[2];
    const float* Wv = (const float*)d_in[3];
    float* out = (float*)d_out;

    cudaFuncSetAttribute(proj_mma, cudaFuncAttributeMaxDynamicSharedMemorySize, PROJ_SMEM);
    cudaFuncSetAttribute(flash_chunk, cudaFuncAttributeMaxDynamicSharedMemorySize, FLASH_SMEM);

    conv_w<<<96, 256>>>(Wq, Wk, Wv);
    proj_mma<<<(BB * TT) / 64, 256, PROJ_SMEM>>>(x);
    flash_chunk<<<dim3(NCHUNK, BB), 256, FLASH_SMEM>>>(out);
    combine_kernel<<<dim3(224, BB), 128>>>(out);
}